// round 1
// baseline (speedup 1.0000x reference)
#include <cuda_runtime.h>

// CIRNet: T=1048576, FEAT=18 (1 time + 1 r0col + 8 sigma feats + 8 eps feats)
// Outputs concatenated: [r_predicts (N), regs (N), dts (N)], N = T-1.
//
// Strategy: Picard (DEER-style) fixed-point iteration. The scan
//   r_{i+1} = m_i r_i + b_i,  m_i = 1 - k*dt_i,
//   b_i = k*th*dt_i + p_i * sqrt(|r_i * dt_i|),  p_i = sig_i * eps_i
// is nonlinear only through sqrt(|r_i|), whose coupling is ~5e-5/step while the
// linear propagator mean-reverts over ~1/(k dt) steps. Evaluating sqrt at the
// previous iterate turns each sweep into a fully parallel affine scan.
// 1 ODE-only sweep + 5 Picard sweeps -> error <<< 1e-3 tolerance.

#define TMAX        (1 << 20)
#define THREADS     256
#define PER_THREAD  32
#define CHUNK       (THREADS * PER_THREAD)   // 8192 elements per block
#define MAXBLOCKS   256                      // TMAX/CHUNK = 128

// scratch (static __device__ globals: allocation-free)
__device__ float g_dt[TMAX];                 // dt_i, padded with 0
__device__ float g_p[TMAX];                  // sig_i*eps_i, padded with 0
__device__ float g_rA[TMAX + 8];             // state buffers: slot i = state ENTERING step i
__device__ float g_rB[TMAX + 8];
__device__ float g_tM[TMAX / PER_THREAD];    // per-thread exclusive prefix (M)
__device__ float g_tB[TMAX / PER_THREAD];    // per-thread exclusive prefix (B)
__device__ float g_bM[MAXBLOCKS];            // per-block total (M)
__device__ float g_bB[MAXBLOCKS];            // per-block total (B)
__device__ float g_Rs[MAXBLOCKS];            // per-block start state

// ---------------------------------------------------------------------------
// Pass 0: per-element precompute. Reads the 76MB trace once.
// Emits dt, p = sig*eps to scratch; regs and dts straight to out.
// Also seeds r-state slot 0 (= r0) and the padding element.
// ---------------------------------------------------------------------------
__global__ void precompute_kernel(
    const float* __restrict__ trace,
    const float* __restrict__ sW, const float* __restrict__ sb,
    const float* __restrict__ eW,
    const float* __restrict__ kp, const float* __restrict__ thp,
    float* __restrict__ out, int N)
{
    int i = blockIdx.x * blockDim.x + threadIdx.x;
    if (i == 0) {
        float r0 = trace[1];      // trace_data[0,1]
        g_rA[0] = r0;
        g_rB[0] = r0;
    }
    if (i >= N) {
        if (i == N && N < TMAX) { g_dt[N] = 0.0f; g_p[N] = 0.0f; }  // identity pad
        return;
    }

    const float* row = trace + (long long)i * 18;
    float t0 = row[0];
    float t1 = row[18];
    float dt = t1 - t0;

    // sig = row[2:10] . sW + sb ;  eps = row[10:18] . eW
    const float2* c2 = reinterpret_cast<const float2*>(row + 2);   // 8B-aligned
    float2 a0 = c2[0], a1 = c2[1], a2 = c2[2], a3 = c2[3];
    float2 b0 = c2[4], b1 = c2[5], b2 = c2[6], b3 = c2[7];

    float sig = sb[0];
    sig = fmaf(a0.x, sW[0], sig); sig = fmaf(a0.y, sW[1], sig);
    sig = fmaf(a1.x, sW[2], sig); sig = fmaf(a1.y, sW[3], sig);
    sig = fmaf(a2.x, sW[4], sig); sig = fmaf(a2.y, sW[5], sig);
    sig = fmaf(a3.x, sW[6], sig); sig = fmaf(a3.y, sW[7], sig);

    float eps = 0.0f;
    eps = fmaf(b0.x, eW[0], eps); eps = fmaf(b0.y, eW[1], eps);
    eps = fmaf(b1.x, eW[2], eps); eps = fmaf(b1.y, eW[3], eps);
    eps = fmaf(b2.x, eW[4], eps); eps = fmaf(b2.y, eW[5], eps);
    eps = fmaf(b3.x, eW[6], eps); eps = fmaf(b3.y, eW[7], eps);

    float kk = kp[0], th = thp[0];

    g_dt[i] = dt;
    g_p[i]  = sig * eps;

    out[N + i]     = (2.0f * kk) * th - sig * sig;   // regs
    out[2 * N + i] = dt;                             // dts
}

// ---------------------------------------------------------------------------
// Phase 1: per-thread affine compose over its 32-element segment, block scan
// (Hillis-Steele over 256 pairs), store per-thread exclusive prefixes and
// per-block totals.
// ---------------------------------------------------------------------------
template <bool USE_SDE>
__global__ void scan_phase1(
    int prevSel,
    const float* __restrict__ kp, const float* __restrict__ thp, int N)
{
    __shared__ float sM[THREADS], sB[THREADS];
    const float kk = kp[0], th = thp[0];
    const float kth = kk * th;

    const float* __restrict__ rprev = prevSel ? g_rB : g_rA;

    int blk = blockIdx.x, tid = threadIdx.x;
    int base = blk * CHUNK + tid * PER_THREAD;

    float M = 1.0f, B = 0.0f;
    if (base < N) {
        const float4* dt4 = reinterpret_cast<const float4*>(g_dt + base);
        const float4* p4  = reinterpret_cast<const float4*>(g_p + base);
        const float4* r4  = reinterpret_cast<const float4*>(rprev + base);
        #pragma unroll
        for (int q = 0; q < PER_THREAD / 4; q++) {
            float4 d = dt4[q];
            float4 pv, rv;
            if (USE_SDE) { pv = p4[q]; rv = r4[q]; }
            float dd[4] = {d.x, d.y, d.z, d.w};
            float ppv[4], rrv[4];
            if (USE_SDE) {
                ppv[0] = pv.x; ppv[1] = pv.y; ppv[2] = pv.z; ppv[3] = pv.w;
                rrv[0] = rv.x; rrv[1] = rv.y; rrv[2] = rv.z; rrv[3] = rv.w;
            }
            #pragma unroll
            for (int u = 0; u < 4; u++) {
                float dt = dd[u];
                float m  = fmaf(-kk, dt, 1.0f);
                float b  = kth * dt;
                if (USE_SDE)
                    b = fmaf(ppv[u], sqrtf(fabsf(rrv[u] * dt)), b);
                B = fmaf(m, B, b);
                M *= m;
            }
        }
    }

    sM[tid] = M; sB[tid] = B;
    __syncthreads();
    #pragma unroll
    for (int off = 1; off < THREADS; off <<= 1) {
        float m = sM[tid], b = sB[tid];
        float pm = 1.0f, pb = 0.0f;
        if (tid >= off) { pm = sM[tid - off]; pb = sB[tid - off]; }
        __syncthreads();
        sM[tid] = m * pm;
        sB[tid] = fmaf(m, pb, b);
        __syncthreads();
    }

    float Mpre = 1.0f, Bpre = 0.0f;
    if (tid > 0) { Mpre = sM[tid - 1]; Bpre = sB[tid - 1]; }
    g_tM[blk * THREADS + tid] = Mpre;
    g_tB[blk * THREADS + tid] = Bpre;
    if (tid == THREADS - 1) { g_bM[blk] = sM[tid]; g_bB[blk] = sB[tid]; }
}

// ---------------------------------------------------------------------------
// Phase 2: sequential combine over the (<=128) per-block pairs.
// ---------------------------------------------------------------------------
__global__ void scan_phase2(const float* __restrict__ trace, int nblk)
{
    __shared__ float sm[MAXBLOCKS], sb2[MAXBLOCKS];
    int tid = threadIdx.x;
    for (int j = tid; j < nblk; j += blockDim.x) { sm[j] = g_bM[j]; sb2[j] = g_bB[j]; }
    __syncthreads();
    if (tid == 0) {
        float R = trace[1];                    // r0
        for (int j = 0; j < nblk; j++) {
            g_Rs[j] = R;
            R = fmaf(sm[j], R, sb2[j]);
        }
    }
}

// ---------------------------------------------------------------------------
// Phase 3: seed each thread from its exclusive prefix + block start, replay
// its 32 steps, write the next-iterate state buffer (shifted by one slot)
// and, on the final sweep, r_predicts to out.
// ---------------------------------------------------------------------------
template <bool USE_SDE>
__global__ void scan_phase3(
    int prevSel, int nextSel, float* __restrict__ outr,
    const float* __restrict__ kp, const float* __restrict__ thp, int N)
{
    int blk = blockIdx.x, tid = threadIdx.x;
    int base = blk * CHUNK + tid * PER_THREAD;
    if (base >= N) return;

    const float kk = kp[0], th = thp[0];
    const float kth = kk * th;

    const float* __restrict__ rprev = prevSel ? g_rB : g_rA;
    float* __restrict__ rnext = (nextSel < 0) ? nullptr : (nextSel ? g_rB : g_rA);

    float r = fmaf(g_tM[blk * THREADS + tid], g_Rs[blk], g_tB[blk * THREADS + tid]);

    const float4* dt4 = reinterpret_cast<const float4*>(g_dt + base);
    const float4* p4  = reinterpret_cast<const float4*>(g_p + base);
    const float4* r4  = reinterpret_cast<const float4*>(rprev + base);

    #pragma unroll
    for (int q = 0; q < PER_THREAD / 4; q++) {
        float4 d = dt4[q];
        float4 pv, rv;
        if (USE_SDE) { pv = p4[q]; rv = r4[q]; }
        float dd[4] = {d.x, d.y, d.z, d.w};
        float ppv[4], rrv[4];
        if (USE_SDE) {
            ppv[0] = pv.x; ppv[1] = pv.y; ppv[2] = pv.z; ppv[3] = pv.w;
            rrv[0] = rv.x; rrv[1] = rv.y; rrv[2] = rv.z; rrv[3] = rv.w;
        }
        #pragma unroll
        for (int u = 0; u < 4; u++) {
            int idx = base + q * 4 + u;
            float dt = dd[u];
            float m  = fmaf(-kk, dt, 1.0f);
            float b  = kth * dt;
            if (USE_SDE)
                b = fmaf(ppv[u], sqrtf(fabsf(rrv[u] * dt)), b);
            r = fmaf(m, r, b);
            if (rnext) rnext[idx + 1] = r;          // slot i+1 = state entering step i+1
            if (outr && idx < N) outr[idx] = r;     // r_predicts[i]
        }
    }
}

// ---------------------------------------------------------------------------
extern "C" void kernel_launch(void* const* d_in, const int* in_sizes, int n_in,
                              void* d_out, int out_size)
{
    const float* trace = (const float*)d_in[0];
    const float* sW    = (const float*)d_in[1];
    const float* sb    = (const float*)d_in[2];
    const float* eW    = (const float*)d_in[3];
    const float* kp    = (const float*)d_in[4];
    const float* thp   = (const float*)d_in[5];
    float* out = (float*)d_out;

    int N = out_size / 3;                    // T-1 = 1048575
    int nblk = (N + CHUNK - 1) / CHUNK;      // 128
    int gpre = (N + 1 + 255) / 256;

    precompute_kernel<<<gpre, 256>>>(trace, sW, sb, eW, kp, thp, out, N);

    // Sweep 0: pure ODE (linear) scan -> buffer A. Deterministic initial iterate.
    scan_phase1<false><<<nblk, THREADS>>>(0, kp, thp, N);
    scan_phase2<<<1, 128>>>(trace, nblk);
    scan_phase3<false><<<nblk, THREADS>>>(0, /*next=*/0, nullptr, kp, thp, N);

    // Sweeps 1..5: Picard iterations with sqrt(|r_prev * dt|).
    int prev = 0;
    for (int s = 1; s <= 5; s++) {
        int next = (s == 5) ? -1 : (1 - prev);
        scan_phase1<true><<<nblk, THREADS>>>(prev, kp, thp, N);
        scan_phase2<<<1, 128>>>(trace, nblk);
        scan_phase3<true><<<nblk, THREADS>>>(prev, next,
                                             (s == 5) ? out : nullptr,
                                             kp, thp, N);
        if (next >= 0) prev = next;
    }
}

// round 2
// speedup vs baseline: 2.3501x; 2.3501x over previous
#include <cuda_runtime.h>

// CIRNet: T=2^20 rows x 18 feats. out = [r_predicts(N), regs(N), dts(N)], N=T-1.
//
// Single persistent kernel:
//   Phase A: stage trace tiles into smem (coalesced float4), compute dt, p=sig*eps,
//            write regs/dts, keep dt/p in smem then registers.
//   Phase B: 6 sweeps (1 ODE + 5 Picard). Each sweep is an affine scan
//            r_{i+1} = m_i r + b_i done with warp scan + block scan + decoupled
//            lookback across the 128 blocks (all resident in one wave).
//            The next sweep's b-coefficients are computed in-register during the
//            replay (r in register IS the state entering step i). No HBM traffic
//            between sweeps except the 128-entry flag/aggregate arrays.
// A second tiny kernel clears the lookback flags for the next graph replay.

#define FEAT      18
#define THREADS   1024
#define PER_TH    8
#define CHUNK     (THREADS * PER_TH)      // 8192 elements per block
#define TILE_ROWS 1024
#define NTILES    (CHUNK / TILE_ROWS)     // 8
#define MAXBLK    128
#define NSWEEP    6                        // sweep 0 = ODE, sweeps 1..5 Picard

__device__ volatile int   g_flag[NSWEEP][MAXBLK];   // 0 none, 1 aggregate, 2 inclusive
__device__ volatile float g_aggM[NSWEEP][MAXBLK];
__device__ volatile float g_aggB[NSWEEP][MAXBLK];
__device__ volatile float g_incR[NSWEEP][MAXBLK];   // block's outgoing state

extern "C" __global__ void __launch_bounds__(THREADS, 1)
cir_main(const float* __restrict__ trace,
         const float* __restrict__ sW, const float* __restrict__ sb,
         const float* __restrict__ eW,
         const float* __restrict__ kp, const float* __restrict__ thp,
         float* __restrict__ out, int N)
{
    extern __shared__ float sm[];
    float* s_dt    = sm;                       // [CHUNK]
    float* s_p     = sm + CHUNK;               // [CHUNK]
    float* s_stage = sm + 2 * CHUNK;           // [TILE_ROWS*FEAT]
    float* s_wM    = s_stage + TILE_ROWS * FEAT;  // [32]
    float* s_wB    = s_wM + 32;                   // [32]
    float* s_rin   = s_wB + 32;                   // [1]

    const int tid  = threadIdx.x;
    const int blk  = blockIdx.x;
    const int lane = tid & 31;
    const int warp = tid >> 5;

    const float kk  = kp[0], th = thp[0];
    const float kth = kk * th;
    const float r0v = trace[1];               // trace_data[0,1]

    // ------------------------- Phase A: precompute -------------------------
    {
        float wS[8], wE[8];
        #pragma unroll
        for (int q = 0; q < 8; q++) { wS[q] = sW[q]; wE[q] = eW[q]; }
        const float sbv = sb[0];
        const int rows_base = blk * CHUNK;

        for (int tl = 0; tl < NTILES; tl++) {
            const int tbase = rows_base + tl * TILE_ROWS;
            const float4* slab = reinterpret_cast<const float4*>(trace) +
                                 (size_t)tbase * FEAT / 4;
            float4* st4 = reinterpret_cast<float4*>(s_stage);
            for (int k = tid; k < TILE_ROWS * FEAT / 4; k += THREADS)
                st4[k] = slab[k];
            __syncthreads();

            const int i = tbase + tid;
            float dt = 0.0f, p = 0.0f;
            if (i < N) {
                const float* row = s_stage + tid * FEAT;
                float tc = row[0];
                float tn = (tid < TILE_ROWS - 1) ? row[FEAT]
                                                 : trace[(size_t)(i + 1) * FEAT];
                dt = tn - tc;
                float sig = sbv, eps = 0.0f;
                #pragma unroll
                for (int q = 0; q < 8; q++) {
                    sig = fmaf(row[2 + q],  wS[q], sig);
                    eps = fmaf(row[10 + q], wE[q], eps);
                }
                p = sig * eps;
                out[N + i]     = fmaf(2.0f * kk, th, -sig * sig);  // regs
                out[2 * N + i] = dt;                               // dts
            }
            s_dt[tl * TILE_ROWS + tid] = dt;
            s_p [tl * TILE_ROWS + tid] = p;
            __syncthreads();
        }
    }

    // Per-thread contiguous segment -> registers (persist across all sweeps)
    const int eb = tid * PER_TH;
    float ldt[PER_TH], lp[PER_TH], lb[PER_TH];
    #pragma unroll
    for (int u = 0; u < PER_TH; u++) {
        ldt[u] = s_dt[eb + u];
        lp[u]  = s_p[eb + u];
        lb[u]  = kth * ldt[u];     // sweep-0 (ODE) b-coefficient
    }

    // --------------------------- Phase B: sweeps ---------------------------
    for (int j = 0; j < NSWEEP; j++) {
        const bool last = (j == NSWEEP - 1);

        // local affine compose over the thread's PER_TH steps
        float M = 1.0f, B = 0.0f;
        #pragma unroll
        for (int u = 0; u < PER_TH; u++) {
            float m = fmaf(-kk, ldt[u], 1.0f);
            B = fmaf(m, B, lb[u]);
            M *= m;
        }

        // warp inclusive scan of transforms (lower lane applied first)
        float iM = M, iB = B;
        #pragma unroll
        for (int off = 1; off < 32; off <<= 1) {
            float pm = __shfl_up_sync(0xFFFFFFFFu, iM, off);
            float pb = __shfl_up_sync(0xFFFFFFFFu, iB, off);
            if (lane >= off) { iB = fmaf(iM, pb, iB); iM *= pm; }
        }
        float eM = __shfl_up_sync(0xFFFFFFFFu, iM, 1);
        float eB = __shfl_up_sync(0xFFFFFFFFu, iB, 1);
        if (lane == 0) { eM = 1.0f; eB = 0.0f; }
        if (lane == 31) { s_wM[warp] = iM; s_wB[warp] = iB; }
        __syncthreads();

        if (warp == 0) {
            // scan the 32 warp aggregates
            float jM = s_wM[lane], jB = s_wB[lane];
            #pragma unroll
            for (int off = 1; off < 32; off <<= 1) {
                float pm = __shfl_up_sync(0xFFFFFFFFu, jM, off);
                float pb = __shfl_up_sync(0xFFFFFFFFu, jB, off);
                if (lane >= off) { jB = fmaf(jM, pb, jB); jM *= pm; }
            }
            float xM = __shfl_up_sync(0xFFFFFFFFu, jM, 1);
            float xB = __shfl_up_sync(0xFFFFFFFFu, jB, 1);
            if (lane == 0) { xM = 1.0f; xB = 0.0f; }
            s_wM[lane] = xM; s_wB[lane] = xB;     // exclusive warp prefixes
            float Mblk = __shfl_sync(0xFFFFFFFFu, jM, 31);
            float Bblk = __shfl_sync(0xFFFFFFFFu, jB, 31);

            // decoupled lookback -> incoming state r_in for this block
            float rin;
            if (blk == 0) {
                rin = r0v;
            } else {
                if (lane == 0) {
                    g_aggM[j][blk] = Mblk; g_aggB[j][blk] = Bblk;
                    __threadfence();
                    g_flag[j][blk] = 1;
                }
                float Mc = 1.0f, Bc = 0.0f;   // maps r_in(idx+1) -> r_in(blk)
                int idx = blk - 1;
                for (;;) {
                    int jj = idx - lane;
                    int fl = 1; float Mv = 1.0f, Bv = 0.0f;
                    if (jj >= 0) {
                        do { fl = g_flag[j][jj]; } while (fl == 0);
                        __threadfence();
                        if (fl == 2) { Mv = 0.0f; Bv = g_incR[j][jj]; }
                        else         { Mv = g_aggM[j][jj]; Bv = g_aggB[j][jj]; }
                    }
                    unsigned bal = __ballot_sync(0xFFFFFFFFu, (jj >= 0) && (fl == 2));
                    if (bal) {
                        int ls = __ffs(bal) - 1;     // nearest inclusive block
                        if (lane > ls) { Mv = 1.0f; Bv = 0.0f; }
                    }
                    // ordered reduction (lane0 outermost), ascending offsets keep order
                    #pragma unroll
                    for (int off = 1; off < 32; off <<= 1) {
                        float Mo = __shfl_down_sync(0xFFFFFFFFu, Mv, off);
                        float Bo = __shfl_down_sync(0xFFFFFFFFu, Bv, off);
                        if (lane + off < 32) { Bv = fmaf(Mv, Bo, Bv); Mv *= Mo; }
                    }
                    if (lane == 0) { Bc = fmaf(Mc, Bv, Bc); Mc *= Mv; }
                    if (bal) break;
                    idx -= 32;
                }
                rin = __shfl_sync(0xFFFFFFFFu, Bc, 0);
            }
            if (lane == 0) {
                g_incR[j][blk] = fmaf(Mblk, rin, Bblk);
                __threadfence();
                g_flag[j][blk] = 2;
                *s_rin = rin;
            }
        }
        __syncthreads();

        // seed this thread's state and replay its steps
        const float rin = *s_rin;
        const float wm = s_wM[warp], wb = s_wB[warp];
        float r = fmaf(eM * wm, rin, fmaf(eM, wb, eB));

        if (last) {
            float ro[PER_TH];
            #pragma unroll
            for (int u = 0; u < PER_TH; u++) {
                float m = fmaf(-kk, ldt[u], 1.0f);
                r = fmaf(m, r, lb[u]);
                ro[u] = r;                         // r_predicts[i] = r_{i+1}
            }
            const int gi = blk * CHUNK + eb;
            if (gi + PER_TH <= N) {
                float4* o4 = reinterpret_cast<float4*>(out + gi);
                o4[0] = make_float4(ro[0], ro[1], ro[2], ro[3]);
                o4[1] = make_float4(ro[4], ro[5], ro[6], ro[7]);
            } else {
                for (int u = 0; u < PER_TH; u++)
                    if (gi + u < N) out[gi + u] = ro[u];
            }
        } else {
            #pragma unroll
            for (int u = 0; u < PER_TH; u++) {
                float m  = fmaf(-kk, ldt[u], 1.0f);
                float bc = lb[u];
                // next sweep's b uses r^{(j)}_i = current r (state entering step i)
                lb[u] = fmaf(lp[u], sqrtf(fabsf(r * ldt[u])), kth * ldt[u]);
                r = fmaf(m, r, bc);
            }
        }
        __syncthreads();   // protect s_wM/s_rin reuse by the next sweep
    }
}

// Reset lookback flags so the next launch/replay starts clean.
extern "C" __global__ void cir_cleanup()
{
    int i = threadIdx.x;
    if (i < NSWEEP * MAXBLK) {
        volatile int* f = &g_flag[0][0];
        f[i] = 0;
    }
}

// ---------------------------------------------------------------------------
extern "C" void kernel_launch(void* const* d_in, const int* in_sizes, int n_in,
                              void* d_out, int out_size)
{
    const float* trace = (const float*)d_in[0];
    const float* sW    = (const float*)d_in[1];
    const float* sb    = (const float*)d_in[2];
    const float* eW    = (const float*)d_in[3];
    const float* kp    = (const float*)d_in[4];
    const float* thp   = (const float*)d_in[5];
    float* out = (float*)d_out;

    int N    = out_size / 3;                       // 1048575
    int nblk = (N + CHUNK - 1) / CHUNK;            // 128 (one wave, 1 block/SM)

    size_t shbytes = (size_t)(2 * CHUNK + TILE_ROWS * FEAT + 68) * sizeof(float);
    cudaFuncSetAttribute(cir_main, cudaFuncAttributeMaxDynamicSharedMemorySize,
                         (int)shbytes);

    cir_main<<<nblk, THREADS, shbytes>>>(trace, sW, sb, eW, kp, thp, out, N);
    cir_cleanup<<<1, NSWEEP * MAXBLK>>>();
}

// round 3
// speedup vs baseline: 3.2767x; 1.3943x over previous
#include <cuda_runtime.h>
#include <cstdint>

// CIRNet: T=2^20 rows x 18 feats. out = [r_predicts(N), regs(N), dts(N)], N=T-1.
// Single persistent kernel, one wave (128 CTAs / 148 SMs):
//   Phase A: double-buffered cp.async tile staging of the 76MB trace,
//            compute dt, p=sig*eps, write regs/dts, keep dt/p in smem->regs.
//   Phase B: 4 sweeps (1 ODE + 3 Picard) of the affine scan
//            r_{i+1} = m_i r + b_i via warp scan + block scan + decoupled
//            lookback (flags in __device__ globals). Next sweep's b computed
//            in-register during replay. Flags cleared at kernel entry
//            (all CTAs co-resident; clear happens ~15us before first use).

#define FEAT      18
#define THREADS   1024
#define PER_TH    8
#define CHUNK     (THREADS * PER_TH)      // 8192 elements per block
#define TILE_ROWS 1024
#define NTILES    (CHUNK / TILE_ROWS)     // 8
#define TILE_VEC  (TILE_ROWS * FEAT / 4)  // 4608 float4 per tile
#define MAXBLK    128
#define NSWEEP    4                        // sweep 0 = ODE, 1..3 Picard

__device__ volatile int   g_flag[NSWEEP][MAXBLK];   // 0 none, 1 aggregate, 2 inclusive
__device__ volatile float g_aggM[NSWEEP][MAXBLK];
__device__ volatile float g_aggB[NSWEEP][MAXBLK];
__device__ volatile float g_incR[NSWEEP][MAXBLK];   // block's outgoing state

__device__ __forceinline__ void cp_async16(float* smem_dst, const float4* gmem_src) {
    uint32_t s = (uint32_t)__cvta_generic_to_shared(smem_dst);
    asm volatile("cp.async.cg.shared.global [%0], [%1], 16;\n"
                 :: "r"(s), "l"(gmem_src) : "memory");
}
#define CP_COMMIT()  asm volatile("cp.async.commit_group;\n" ::: "memory")
#define CP_WAIT(n)   asm volatile("cp.async.wait_group %0;\n" :: "n"(n) : "memory")

extern "C" __global__ void __launch_bounds__(THREADS, 1)
cir_main(const float* __restrict__ trace,
         const float* __restrict__ sW, const float* __restrict__ sb,
         const float* __restrict__ eW,
         const float* __restrict__ kp, const float* __restrict__ thp,
         float* __restrict__ out, int N)
{
    extern __shared__ float sm[];
    float* s_dt   = sm;                          // [CHUNK]
    float* s_p    = sm + CHUNK;                  // [CHUNK]
    float* s_stg0 = sm + 2 * CHUNK;              // [TILE_ROWS*FEAT]
    float* s_stg1 = s_stg0 + TILE_ROWS * FEAT;   // [TILE_ROWS*FEAT]
    float* s_wM   = s_stg1 + TILE_ROWS * FEAT;   // [32]
    float* s_wB   = s_wM + 32;                   // [32]
    float* s_rin  = s_wB + 32;                   // [1]

    const int tid  = threadIdx.x;
    const int blk  = blockIdx.x;
    const int lane = tid & 31;
    const int warp = tid >> 5;

    // ---- clear this block's lookback flags (used >>10us later; all CTAs
    //      of the single wave start within <1us of each other) ----
    if (tid < NSWEEP) g_flag[tid][blk] = 0;
    __threadfence();

    const float kk  = kp[0], th = thp[0];
    const float kth = kk * th;
    const float r0v = trace[1];                  // trace_data[0,1]

    // ------------------------- Phase A: precompute -------------------------
    {
        float wS[8], wE[8];
        #pragma unroll
        for (int q = 0; q < 8; q++) { wS[q] = sW[q]; wE[q] = eW[q]; }
        const float sbv = sb[0];
        const int rows_base = blk * CHUNK;
        const float4* tr4 = reinterpret_cast<const float4*>(trace);

        // prologue: tile 0 -> buf0
        {
            const float4* slab = tr4 + (size_t)rows_base * FEAT / 4;
            for (int k = tid; k < TILE_VEC; k += THREADS)
                cp_async16(s_stg0 + 4 * k, slab + k);
            CP_COMMIT();
        }

        for (int tl = 0; tl < NTILES; tl++) {
            float* buf = (tl & 1) ? s_stg1 : s_stg0;
            if (tl + 1 < NTILES) {
                float* nbuf = ((tl + 1) & 1) ? s_stg1 : s_stg0;
                const float4* slab = tr4 +
                    (size_t)(rows_base + (tl + 1) * TILE_ROWS) * FEAT / 4;
                for (int k = tid; k < TILE_VEC; k += THREADS)
                    cp_async16(nbuf + 4 * k, slab + k);
                CP_COMMIT();
                CP_WAIT(1);          // tile tl complete
            } else {
                CP_WAIT(0);
            }
            __syncthreads();

            const int i = rows_base + tl * TILE_ROWS + tid;
            float dt = 0.0f, p = 0.0f;
            if (i < N) {
                const float* row = buf + tid * FEAT;
                float tc = row[0];
                float tn = (tid < TILE_ROWS - 1) ? row[FEAT]
                                                 : trace[(size_t)(i + 1) * FEAT];
                dt = tn - tc;
                float sig = sbv, eps = 0.0f;
                #pragma unroll
                for (int q = 0; q < 8; q++) {
                    sig = fmaf(row[2 + q],  wS[q], sig);
                    eps = fmaf(row[10 + q], wE[q], eps);
                }
                p = sig * eps;
                out[N + i]     = fmaf(2.0f * kk, th, -sig * sig);  // regs
                out[2 * N + i] = dt;                               // dts
            }
            s_dt[tl * TILE_ROWS + tid] = dt;
            s_p [tl * TILE_ROWS + tid] = p;
            __syncthreads();
        }
    }

    // Per-thread contiguous segment -> registers (persist across all sweeps)
    const int eb = tid * PER_TH;
    float ldt[PER_TH], lp[PER_TH], lb[PER_TH];
    #pragma unroll
    for (int u = 0; u < PER_TH; u++) {
        ldt[u] = s_dt[eb + u];
        lp[u]  = s_p[eb + u];
        lb[u]  = kth * ldt[u];       // sweep-0 (ODE) b-coefficient
    }

    // --------------------------- Phase B: sweeps ---------------------------
    for (int j = 0; j < NSWEEP; j++) {
        const bool last = (j == NSWEEP - 1);

        // local affine compose over the thread's PER_TH steps
        float M = 1.0f, B = 0.0f;
        #pragma unroll
        for (int u = 0; u < PER_TH; u++) {
            float m = fmaf(-kk, ldt[u], 1.0f);
            B = fmaf(m, B, lb[u]);
            M *= m;
        }

        // warp inclusive scan of transforms (lower lane applied first)
        float iM = M, iB = B;
        #pragma unroll
        for (int off = 1; off < 32; off <<= 1) {
            float pm = __shfl_up_sync(0xFFFFFFFFu, iM, off);
            float pb = __shfl_up_sync(0xFFFFFFFFu, iB, off);
            if (lane >= off) { iB = fmaf(iM, pb, iB); iM *= pm; }
        }
        float eM = __shfl_up_sync(0xFFFFFFFFu, iM, 1);
        float eB = __shfl_up_sync(0xFFFFFFFFu, iB, 1);
        if (lane == 0) { eM = 1.0f; eB = 0.0f; }
        if (lane == 31) { s_wM[warp] = iM; s_wB[warp] = iB; }
        __syncthreads();

        if (warp == 0) {
            // scan the 32 warp aggregates
            float jM = s_wM[lane], jB = s_wB[lane];
            #pragma unroll
            for (int off = 1; off < 32; off <<= 1) {
                float pm = __shfl_up_sync(0xFFFFFFFFu, jM, off);
                float pb = __shfl_up_sync(0xFFFFFFFFu, jB, off);
                if (lane >= off) { jB = fmaf(jM, pb, jB); jM *= pm; }
            }
            float xM = __shfl_up_sync(0xFFFFFFFFu, jM, 1);
            float xB = __shfl_up_sync(0xFFFFFFFFu, jB, 1);
            if (lane == 0) { xM = 1.0f; xB = 0.0f; }
            s_wM[lane] = xM; s_wB[lane] = xB;     // exclusive warp prefixes
            float Mblk = __shfl_sync(0xFFFFFFFFu, jM, 31);
            float Bblk = __shfl_sync(0xFFFFFFFFu, jB, 31);

            // decoupled lookback -> incoming state r_in for this block
            float rin;
            if (blk == 0) {
                rin = r0v;
            } else {
                if (lane == 0) {
                    g_aggM[j][blk] = Mblk; g_aggB[j][blk] = Bblk;
                    __threadfence();
                    g_flag[j][blk] = 1;
                }
                float Mc = 1.0f, Bc = 0.0f;   // maps r_in(idx+1) -> r_in(blk)
                int idx = blk - 1;
                for (;;) {
                    int jj = idx - lane;
                    int fl = 1; float Mv = 1.0f, Bv = 0.0f;
                    if (jj >= 0) {
                        do { fl = g_flag[j][jj]; } while (fl == 0);
                        __threadfence();
                        if (fl == 2) { Mv = 0.0f; Bv = g_incR[j][jj]; }
                        else         { Mv = g_aggM[j][jj]; Bv = g_aggB[j][jj]; }
                    }
                    unsigned bal = __ballot_sync(0xFFFFFFFFu, (jj >= 0) && (fl == 2));
                    if (bal) {
                        int ls = __ffs(bal) - 1;     // nearest inclusive block
                        if (lane > ls) { Mv = 1.0f; Bv = 0.0f; }
                    }
                    // ordered reduction (lane0 outermost)
                    #pragma unroll
                    for (int off = 1; off < 32; off <<= 1) {
                        float Mo = __shfl_down_sync(0xFFFFFFFFu, Mv, off);
                        float Bo = __shfl_down_sync(0xFFFFFFFFu, Bv, off);
                        if (lane + off < 32) { Bv = fmaf(Mv, Bo, Bv); Mv *= Mo; }
                    }
                    if (lane == 0) { Bc = fmaf(Mc, Bv, Bc); Mc *= Mv; }
                    if (bal) break;
                    idx -= 32;
                }
                rin = __shfl_sync(0xFFFFFFFFu, Bc, 0);
            }
            if (lane == 0) {
                g_incR[j][blk] = fmaf(Mblk, rin, Bblk);
                __threadfence();
                g_flag[j][blk] = 2;
                *s_rin = rin;
            }
        }
        __syncthreads();

        // seed this thread's state and replay its steps
        const float rin = *s_rin;
        const float wm = s_wM[warp], wb = s_wB[warp];
        float r = fmaf(eM * wm, rin, fmaf(eM, wb, eB));

        if (last) {
            float ro[PER_TH];
            #pragma unroll
            for (int u = 0; u < PER_TH; u++) {
                float m = fmaf(-kk, ldt[u], 1.0f);
                r = fmaf(m, r, lb[u]);
                ro[u] = r;                         // r_predicts[i] = r_{i+1}
            }
            const int gi = blk * CHUNK + eb;
            if (gi + PER_TH <= N) {
                float4* o4 = reinterpret_cast<float4*>(out + gi);
                o4[0] = make_float4(ro[0], ro[1], ro[2], ro[3]);
                o4[1] = make_float4(ro[4], ro[5], ro[6], ro[7]);
            } else {
                for (int u = 0; u < PER_TH; u++)
                    if (gi + u < N) out[gi + u] = ro[u];
            }
        } else {
            #pragma unroll
            for (int u = 0; u < PER_TH; u++) {
                float m  = fmaf(-kk, ldt[u], 1.0f);
                float bc = lb[u];
                // next sweep's b uses r^{(j)}_i = current r (state entering step i)
                lb[u] = fmaf(lp[u], sqrtf(fabsf(r * ldt[u])), kth * ldt[u]);
                r = fmaf(m, r, bc);
            }
        }
        __syncthreads();   // protect s_wM/s_rin reuse by the next sweep
    }
}

// ---------------------------------------------------------------------------
extern "C" void kernel_launch(void* const* d_in, const int* in_sizes, int n_in,
                              void* d_out, int out_size)
{
    const float* trace = (const float*)d_in[0];
    const float* sW    = (const float*)d_in[1];
    const float* sb    = (const float*)d_in[2];
    const float* eW    = (const float*)d_in[3];
    const float* kp    = (const float*)d_in[4];
    const float* thp   = (const float*)d_in[5];
    float* out = (float*)d_out;

    int N    = out_size / 3;                       // 1048575
    int nblk = (N + CHUNK - 1) / CHUNK;            // 128 (one wave, 1 CTA/SM)

    size_t shbytes = (size_t)(2 * CHUNK + 2 * TILE_ROWS * FEAT + 68) * sizeof(float);
    cudaFuncSetAttribute(cir_main, cudaFuncAttributeMaxDynamicSharedMemorySize,
                         (int)shbytes);

    cir_main<<<nblk, THREADS, shbytes>>>(trace, sW, sb, eW, kp, thp, out, N);
}

// round 4
// speedup vs baseline: 3.6359x; 1.1096x over previous
#include <cuda_runtime.h>
#include <cstdint>

// CIRNet: T=2^20 rows x 18 feats. out = [r_predicts(N), regs(N), dts(N)], N=T-1.
// Single persistent kernel, one wave (147 CTAs / 148 SMs, 896 thr):
//   Phase A: double-buffered cp.async tile staging of the 76MB trace,
//            compute dt, p=sig*eps, write regs/dts, keep dt/p in smem->regs.
//   Phase B: 3 sweeps (1 ODE + 2 Picard) of the affine scan
//            r_{i+1} = m_i r + b_i via warp scan + block scan + decoupled
//            lookback (flags in __device__ globals, cleared at kernel entry).
//            Next sweep's b computed in-register during replay.

#define FEAT      18
#define THREADS   896
#define NWARP     (THREADS / 32)          // 28
#define PER_TH    8
#define CHUNK     (THREADS * PER_TH)      // 7168 elements per block
#define TILE_ROWS THREADS                 // 896 rows per tile
#define NTILES    (CHUNK / TILE_ROWS)     // 8
#define TILE_VEC  (TILE_ROWS * FEAT / 4)  // 4032 float4 per tile
#define MAXBLK    160
#define NSWEEP    3                        // sweep 0 = ODE, 1..2 Picard

__device__ volatile int   g_flag[NSWEEP][MAXBLK];   // 0 none, 1 aggregate, 2 inclusive
__device__ volatile float g_aggM[NSWEEP][MAXBLK];
__device__ volatile float g_aggB[NSWEEP][MAXBLK];
__device__ volatile float g_incR[NSWEEP][MAXBLK];   // block's outgoing state

__device__ __forceinline__ void cp_async16(float* smem_dst, const float4* gmem_src) {
    uint32_t s = (uint32_t)__cvta_generic_to_shared(smem_dst);
    asm volatile("cp.async.cg.shared.global [%0], [%1], 16;\n"
                 :: "r"(s), "l"(gmem_src) : "memory");
}
#define CP_COMMIT()  asm volatile("cp.async.commit_group;\n" ::: "memory")
#define CP_WAIT(n)   asm volatile("cp.async.wait_group %0;\n" :: "n"(n) : "memory")

extern "C" __global__ void __launch_bounds__(THREADS, 1)
cir_main(const float* __restrict__ trace,
         const float* __restrict__ sW, const float* __restrict__ sb,
         const float* __restrict__ eW,
         const float* __restrict__ kp, const float* __restrict__ thp,
         float* __restrict__ out, int N)
{
    extern __shared__ float sm[];
    float* s_dt   = sm;                          // [CHUNK]
    float* s_p    = sm + CHUNK;                  // [CHUNK]
    float* s_stg0 = sm + 2 * CHUNK;              // [TILE_ROWS*FEAT]
    float* s_stg1 = s_stg0 + TILE_ROWS * FEAT;   // [TILE_ROWS*FEAT]
    float* s_wM   = s_stg1 + TILE_ROWS * FEAT;   // [32]
    float* s_wB   = s_wM + 32;                   // [32]
    float* s_rin  = s_wB + 32;                   // [1]

    const int tid  = threadIdx.x;
    const int blk  = blockIdx.x;
    const int lane = tid & 31;
    const int warp = tid >> 5;

    // clear this block's lookback flags (consumed >>10us later; all CTAs of
    // the single wave start within ~1us of each other)
    if (tid < NSWEEP) g_flag[tid][blk] = 0;
    __threadfence();

    const float kk  = kp[0], th = thp[0];
    const float kth = kk * th;
    const float r0v = trace[1];                  // trace_data[0,1]

    // ------------------------- Phase A: precompute -------------------------
    {
        float wS[8], wE[8];
        #pragma unroll
        for (int q = 0; q < 8; q++) { wS[q] = sW[q]; wE[q] = eW[q]; }
        const float sbv = sb[0];
        const int rows_base = blk * CHUNK;
        const float4* tr4 = reinterpret_cast<const float4*>(trace);
        const size_t tot4 = (size_t)(N + 1) * FEAT / 4;   // total float4 in trace

        // prologue: tile 0 -> buf0
        {
            const size_t sb4 = (size_t)rows_base * FEAT / 4;
            for (int k = tid; k < TILE_VEC; k += THREADS)
                if (sb4 + k < tot4) cp_async16(s_stg0 + 4 * k, tr4 + sb4 + k);
            CP_COMMIT();
        }

        for (int tl = 0; tl < NTILES; tl++) {
            float* buf = (tl & 1) ? s_stg1 : s_stg0;
            if (tl + 1 < NTILES) {
                float* nbuf = ((tl + 1) & 1) ? s_stg1 : s_stg0;
                const size_t sb4 =
                    (size_t)(rows_base + (tl + 1) * TILE_ROWS) * FEAT / 4;
                for (int k = tid; k < TILE_VEC; k += THREADS)
                    if (sb4 + k < tot4) cp_async16(nbuf + 4 * k, tr4 + sb4 + k);
                CP_COMMIT();
                CP_WAIT(1);          // tile tl complete
            } else {
                CP_WAIT(0);
            }
            __syncthreads();

            const int i = rows_base + tl * TILE_ROWS + tid;
            float dt = 0.0f, p = 0.0f;
            if (i < N) {
                const float* row = buf + tid * FEAT;
                float tc = row[0];
                float tn = (tid < TILE_ROWS - 1) ? row[FEAT]
                                                 : trace[(size_t)(i + 1) * FEAT];
                dt = tn - tc;
                float sig = sbv, eps = 0.0f;
                #pragma unroll
                for (int q = 0; q < 8; q++) {
                    sig = fmaf(row[2 + q],  wS[q], sig);
                    eps = fmaf(row[10 + q], wE[q], eps);
                }
                p = sig * eps;
                out[N + i]     = fmaf(2.0f * kk, th, -sig * sig);  // regs
                out[2 * N + i] = dt;                               // dts
            }
            s_dt[tl * TILE_ROWS + tid] = dt;
            s_p [tl * TILE_ROWS + tid] = p;
            __syncthreads();
        }
    }

    // Per-thread contiguous segment -> registers (persist across all sweeps)
    const int eb = tid * PER_TH;
    float ldt[PER_TH], lp[PER_TH], lb[PER_TH];
    #pragma unroll
    for (int u = 0; u < PER_TH; u++) {
        ldt[u] = s_dt[eb + u];
        lp[u]  = s_p[eb + u];
        lb[u]  = kth * ldt[u];       // sweep-0 (ODE) b-coefficient
    }

    // --------------------------- Phase B: sweeps ---------------------------
    for (int j = 0; j < NSWEEP; j++) {
        const bool last = (j == NSWEEP - 1);

        // local affine compose over the thread's PER_TH steps
        float M = 1.0f, B = 0.0f;
        #pragma unroll
        for (int u = 0; u < PER_TH; u++) {
            float m = fmaf(-kk, ldt[u], 1.0f);
            B = fmaf(m, B, lb[u]);
            M *= m;
        }

        // warp inclusive scan of transforms (lower lane applied first)
        float iM = M, iB = B;
        #pragma unroll
        for (int off = 1; off < 32; off <<= 1) {
            float pm = __shfl_up_sync(0xFFFFFFFFu, iM, off);
            float pb = __shfl_up_sync(0xFFFFFFFFu, iB, off);
            if (lane >= off) { iB = fmaf(iM, pb, iB); iM *= pm; }
        }
        float eM = __shfl_up_sync(0xFFFFFFFFu, iM, 1);
        float eB = __shfl_up_sync(0xFFFFFFFFu, iB, 1);
        if (lane == 0) { eM = 1.0f; eB = 0.0f; }
        if (lane == 31) { s_wM[warp] = iM; s_wB[warp] = iB; }
        __syncthreads();

        if (warp == 0) {
            // scan the NWARP warp aggregates (pad to 32 with identity)
            float jM = (lane < NWARP) ? s_wM[lane] : 1.0f;
            float jB = (lane < NWARP) ? s_wB[lane] : 0.0f;
            #pragma unroll
            for (int off = 1; off < 32; off <<= 1) {
                float pm = __shfl_up_sync(0xFFFFFFFFu, jM, off);
                float pb = __shfl_up_sync(0xFFFFFFFFu, jB, off);
                if (lane >= off) { jB = fmaf(jM, pb, jB); jM *= pm; }
            }
            float xM = __shfl_up_sync(0xFFFFFFFFu, jM, 1);
            float xB = __shfl_up_sync(0xFFFFFFFFu, jB, 1);
            if (lane == 0) { xM = 1.0f; xB = 0.0f; }
            if (lane < NWARP) { s_wM[lane] = xM; s_wB[lane] = xB; }
            float Mblk = __shfl_sync(0xFFFFFFFFu, jM, 31);
            float Bblk = __shfl_sync(0xFFFFFFFFu, jB, 31);

            // decoupled lookback -> incoming state r_in for this block
            float rin;
            if (blk == 0) {
                rin = r0v;
            } else {
                if (lane == 0) {
                    g_aggM[j][blk] = Mblk; g_aggB[j][blk] = Bblk;
                    __threadfence();
                    g_flag[j][blk] = 1;
                }
                float Mc = 1.0f, Bc = 0.0f;   // maps r_in(idx+1) -> r_in(blk)
                int idx = blk - 1;
                for (;;) {
                    int jj = idx - lane;
                    int fl = 1; float Mv = 1.0f, Bv = 0.0f;
                    if (jj >= 0) {
                        do { fl = g_flag[j][jj]; } while (fl == 0);
                        __threadfence();
                        if (fl == 2) { Mv = 0.0f; Bv = g_incR[j][jj]; }
                        else         { Mv = g_aggM[j][jj]; Bv = g_aggB[j][jj]; }
                    }
                    unsigned bal = __ballot_sync(0xFFFFFFFFu, (jj >= 0) && (fl == 2));
                    if (bal) {
                        int ls = __ffs(bal) - 1;     // nearest inclusive block
                        if (lane > ls) { Mv = 1.0f; Bv = 0.0f; }
                    }
                    // ordered reduction (lane0 outermost)
                    #pragma unroll
                    for (int off = 1; off < 32; off <<= 1) {
                        float Mo = __shfl_down_sync(0xFFFFFFFFu, Mv, off);
                        float Bo = __shfl_down_sync(0xFFFFFFFFu, Bv, off);
                        if (lane + off < 32) { Bv = fmaf(Mv, Bo, Bv); Mv *= Mo; }
                    }
                    if (lane == 0) { Bc = fmaf(Mc, Bv, Bc); Mc *= Mv; }
                    if (bal) break;
                    idx -= 32;
                }
                rin = __shfl_sync(0xFFFFFFFFu, Bc, 0);
            }
            if (lane == 0) {
                g_incR[j][blk] = fmaf(Mblk, rin, Bblk);
                __threadfence();
                g_flag[j][blk] = 2;
                *s_rin = rin;
            }
        }
        __syncthreads();

        // seed this thread's state and replay its steps
        const float rin = *s_rin;
        const float wm = s_wM[warp], wb = s_wB[warp];
        float r = fmaf(eM * wm, rin, fmaf(eM, wb, eB));

        if (last) {
            float ro[PER_TH];
            #pragma unroll
            for (int u = 0; u < PER_TH; u++) {
                float m = fmaf(-kk, ldt[u], 1.0f);
                r = fmaf(m, r, lb[u]);
                ro[u] = r;                         // r_predicts[i] = r_{i+1}
            }
            const int gi = blk * CHUNK + eb;
            if (gi + PER_TH <= N) {
                float4* o4 = reinterpret_cast<float4*>(out + gi);
                o4[0] = make_float4(ro[0], ro[1], ro[2], ro[3]);
                o4[1] = make_float4(ro[4], ro[5], ro[6], ro[7]);
            } else {
                for (int u = 0; u < PER_TH; u++)
                    if (gi + u < N) out[gi + u] = ro[u];
            }
        } else {
            #pragma unroll
            for (int u = 0; u < PER_TH; u++) {
                float m  = fmaf(-kk, ldt[u], 1.0f);
                float bc = lb[u];
                // next sweep's b uses r^{(j)}_i = current r (state entering step i)
                lb[u] = fmaf(lp[u], sqrtf(fabsf(r * ldt[u])), kth * ldt[u]);
                r = fmaf(m, r, bc);
            }
        }
        __syncthreads();   // protect s_wM/s_rin reuse by the next sweep
    }
}

// ---------------------------------------------------------------------------
extern "C" void kernel_launch(void* const* d_in, const int* in_sizes, int n_in,
                              void* d_out, int out_size)
{
    const float* trace = (const float*)d_in[0];
    const float* sW    = (const float*)d_in[1];
    const float* sb    = (const float*)d_in[2];
    const float* eW    = (const float*)d_in[3];
    const float* kp    = (const float*)d_in[4];
    const float* thp   = (const float*)d_in[5];
    float* out = (float*)d_out;

    int N    = out_size / 3;                       // 1048575
    int nblk = (N + CHUNK - 1) / CHUNK;            // 147 (one wave, 1 CTA/SM)

    size_t shbytes = (size_t)(2 * CHUNK + 2 * TILE_ROWS * FEAT + 68) * sizeof(float);
    cudaFuncSetAttribute(cir_main, cudaFuncAttributeMaxDynamicSharedMemorySize,
                         (int)shbytes);

    cir_main<<<nblk, THREADS, shbytes>>>(trace, sW, sb, eW, kp, thp, out, N);
}

// round 5
// speedup vs baseline: 3.6392x; 1.0009x over previous
#include <cuda_runtime.h>
#include <cstdint>

// CIRNet: T=2^20 rows x 18 feats. out = [r_predicts(N), regs(N), dts(N)], N=T-1.
// Single persistent kernel, one wave (147 CTAs, 896 thr):
//   Phase A: TMA (cp.async.bulk) double-buffered tile staging of the 76MB
//            trace -- ONE bulk copy per 63KB tile instead of 4032 LDGSTS.
//            Compute dt, p=sig*eps, write regs/dts (streaming stores).
//   Phase B: 3 sweeps (1 ODE + 2 Picard) of the affine scan
//            r_{i+1} = m_i r + b_i via warp scan + block scan + decoupled
//            lookback (flags in __device__ globals, cleared at kernel entry).

#define FEAT      18
#define THREADS   896
#define NWARP     (THREADS / 32)          // 28
#define PER_TH    8
#define CHUNK     (THREADS * PER_TH)      // 7168 elements per block
#define TILE_ROWS THREADS                 // 896 rows per tile
#define NTILES    (CHUNK / TILE_ROWS)     // 8
#define TILE_BYTES (TILE_ROWS * FEAT * 4) // 64512 bytes per tile
#define MAXBLK    160
#define NSWEEP    3                        // sweep 0 = ODE, 1..2 Picard

__device__ volatile int   g_flag[NSWEEP][MAXBLK];   // 0 none, 1 aggregate, 2 inclusive
__device__ volatile float g_aggM[NSWEEP][MAXBLK];
__device__ volatile float g_aggB[NSWEEP][MAXBLK];
__device__ volatile float g_incR[NSWEEP][MAXBLK];   // block's outgoing state

__device__ __forceinline__ uint32_t smem_u32(const void* p) {
    return (uint32_t)__cvta_generic_to_shared(p);
}
__device__ __forceinline__ void mbar_init(uint32_t mbar, uint32_t cnt) {
    asm volatile("mbarrier.init.shared.b64 [%0], %1;" :: "r"(mbar), "r"(cnt) : "memory");
}
__device__ __forceinline__ void mbar_expect_tx(uint32_t mbar, uint32_t bytes) {
    asm volatile("mbarrier.arrive.expect_tx.shared.b64 _, [%0], %1;"
                 :: "r"(mbar), "r"(bytes) : "memory");
}
__device__ __forceinline__ void mbar_wait(uint32_t mbar, uint32_t parity) {
    asm volatile(
        "{\n\t.reg .pred P;\n"
        "W%=:\n\t"
        "mbarrier.try_wait.parity.acquire.cta.shared::cta.b64 P, [%0], %1, 0x989680;\n\t"
        "@P bra D%=;\n\t"
        "bra W%=;\n"
        "D%=:\n\t}"
        :: "r"(mbar), "r"(parity) : "memory");
}
__device__ __forceinline__ void tma_bulk_g2s(uint32_t dst_smem, const void* gsrc,
                                             uint32_t bytes, uint32_t mbar) {
    asm volatile(
        "cp.async.bulk.shared::cluster.global.mbarrier::complete_tx::bytes "
        "[%0], [%1], %2, [%3];"
        :: "r"(dst_smem), "l"(gsrc), "r"(bytes), "r"(mbar) : "memory");
}

extern "C" __global__ void __launch_bounds__(THREADS, 1)
cir_main(const float* __restrict__ trace,
         const float* __restrict__ sW, const float* __restrict__ sb,
         const float* __restrict__ eW,
         const float* __restrict__ kp, const float* __restrict__ thp,
         float* __restrict__ out, int N)
{
    extern __shared__ float sm[];
    // [0..3]   : two 8-byte mbarriers (16B-aligned base)
    float* s_bar  = sm;
    float* s_dt   = sm + 4;                       // [CHUNK]
    float* s_p    = s_dt + CHUNK;                 // [CHUNK]
    float* s_stg0 = s_p + CHUNK;                  // [TILE_ROWS*FEAT]
    float* s_stg1 = s_stg0 + TILE_ROWS * FEAT;    // [TILE_ROWS*FEAT]
    float* s_wM   = s_stg1 + TILE_ROWS * FEAT;    // [32]
    float* s_wB   = s_wM + 32;                    // [32]
    float* s_rin  = s_wB + 32;                    // [1]

    const int tid  = threadIdx.x;
    const int blk  = blockIdx.x;
    const int lane = tid & 31;
    const int warp = tid >> 5;

    const uint32_t bar0 = smem_u32(s_bar);
    const uint32_t bar1 = bar0 + 8;

    // clear this block's lookback flags (consumed >>10us later; single wave)
    if (tid < NSWEEP) g_flag[tid][blk] = 0;
    __threadfence();

    if (tid == 0) { mbar_init(bar0, 1); mbar_init(bar1, 1); }
    __syncthreads();

    const float kk  = kp[0], th = thp[0];
    const float kth = kk * th;
    const float r0v = trace[1];                  // trace_data[0,1]

    // ------------------------- Phase A: precompute -------------------------
    {
        float wS[8], wE[8];
        #pragma unroll
        for (int q = 0; q < 8; q++) { wS[q] = sW[q]; wE[q] = eW[q]; }
        const float sbv = sb[0];
        const int rows_base = blk * CHUNK;
        const char* trc = reinterpret_cast<const char*>(trace);
        const long long tot_bytes = (long long)(N + 1) * FEAT * 4;

        // prologue: tile 0 -> buf0
        if (tid == 0) {
            long long start = (long long)rows_base * FEAT * 4;
            long long avail = tot_bytes - start;
            uint32_t sz = (avail <= 0) ? 0u :
                          (avail < TILE_BYTES ? (uint32_t)avail : (uint32_t)TILE_BYTES);
            mbar_expect_tx(bar0, sz);
            if (sz) tma_bulk_g2s(smem_u32(s_stg0), trc + start, sz, bar0);
        }

        for (int tl = 0; tl < NTILES; tl++) {
            float* buf = (tl & 1) ? s_stg1 : s_stg0;
            if (tid == 0 && tl + 1 < NTILES) {
                float* nbuf = ((tl + 1) & 1) ? s_stg1 : s_stg0;
                uint32_t nbar = ((tl + 1) & 1) ? bar1 : bar0;
                long long start = (long long)(rows_base + (tl + 1) * TILE_ROWS) * FEAT * 4;
                long long avail = tot_bytes - start;
                uint32_t sz = (avail <= 0) ? 0u :
                              (avail < TILE_BYTES ? (uint32_t)avail : (uint32_t)TILE_BYTES);
                mbar_expect_tx(nbar, sz);
                if (sz) tma_bulk_g2s(smem_u32(nbuf), trc + start, sz, nbar);
            }
            // wait tile tl: barrier (tl&1), phase (tl>>1)&1
            mbar_wait((tl & 1) ? bar1 : bar0, (tl >> 1) & 1);

            const int i = rows_base + tl * TILE_ROWS + tid;
            float dt = 0.0f, p = 0.0f;
            if (i < N) {
                const float2* row2 = reinterpret_cast<const float2*>(buf + tid * FEAT);
                float tc = row2[0].x;
                float tn = (tid < TILE_ROWS - 1) ? buf[(tid + 1) * FEAT]
                                                 : trace[(size_t)(i + 1) * FEAT];
                dt = tn - tc;
                float sig = sbv, eps = 0.0f;
                #pragma unroll
                for (int q = 0; q < 4; q++) {
                    float2 f = row2[1 + q];
                    sig = fmaf(f.x, wS[2 * q], sig);
                    sig = fmaf(f.y, wS[2 * q + 1], sig);
                }
                #pragma unroll
                for (int q = 0; q < 4; q++) {
                    float2 f = row2[5 + q];
                    eps = fmaf(f.x, wE[2 * q], eps);
                    eps = fmaf(f.y, wE[2 * q + 1], eps);
                }
                p = sig * eps;
                __stcs(&out[N + i],     fmaf(2.0f * kk, th, -sig * sig));  // regs
                __stcs(&out[2 * N + i], dt);                               // dts
            }
            s_dt[tl * TILE_ROWS + tid] = dt;
            s_p [tl * TILE_ROWS + tid] = p;
            __syncthreads();   // all reads of buf done before it is re-filled
        }
    }

    // Per-thread contiguous segment -> registers (persist across all sweeps)
    const int eb = tid * PER_TH;
    float ldt[PER_TH], lp[PER_TH], lb[PER_TH];
    #pragma unroll
    for (int u = 0; u < PER_TH; u++) {
        ldt[u] = s_dt[eb + u];
        lp[u]  = s_p[eb + u];
        lb[u]  = kth * ldt[u];       // sweep-0 (ODE) b-coefficient
    }

    // --------------------------- Phase B: sweeps ---------------------------
    for (int j = 0; j < NSWEEP; j++) {
        const bool last = (j == NSWEEP - 1);

        // local affine compose over the thread's PER_TH steps
        float M = 1.0f, B = 0.0f;
        #pragma unroll
        for (int u = 0; u < PER_TH; u++) {
            float m = fmaf(-kk, ldt[u], 1.0f);
            B = fmaf(m, B, lb[u]);
            M *= m;
        }

        // warp inclusive scan of transforms (lower lane applied first)
        float iM = M, iB = B;
        #pragma unroll
        for (int off = 1; off < 32; off <<= 1) {
            float pm = __shfl_up_sync(0xFFFFFFFFu, iM, off);
            float pb = __shfl_up_sync(0xFFFFFFFFu, iB, off);
            if (lane >= off) { iB = fmaf(iM, pb, iB); iM *= pm; }
        }
        float eM = __shfl_up_sync(0xFFFFFFFFu, iM, 1);
        float eB = __shfl_up_sync(0xFFFFFFFFu, iB, 1);
        if (lane == 0) { eM = 1.0f; eB = 0.0f; }
        if (lane == 31) { s_wM[warp] = iM; s_wB[warp] = iB; }
        __syncthreads();

        if (warp == 0) {
            // scan the NWARP warp aggregates (pad to 32 with identity)
            float jM = (lane < NWARP) ? s_wM[lane] : 1.0f;
            float jB = (lane < NWARP) ? s_wB[lane] : 0.0f;
            #pragma unroll
            for (int off = 1; off < 32; off <<= 1) {
                float pm = __shfl_up_sync(0xFFFFFFFFu, jM, off);
                float pb = __shfl_up_sync(0xFFFFFFFFu, jB, off);
                if (lane >= off) { jB = fmaf(jM, pb, jB); jM *= pm; }
            }
            float xM = __shfl_up_sync(0xFFFFFFFFu, jM, 1);
            float xB = __shfl_up_sync(0xFFFFFFFFu, jB, 1);
            if (lane == 0) { xM = 1.0f; xB = 0.0f; }
            if (lane < NWARP) { s_wM[lane] = xM; s_wB[lane] = xB; }
            float Mblk = __shfl_sync(0xFFFFFFFFu, jM, 31);
            float Bblk = __shfl_sync(0xFFFFFFFFu, jB, 31);

            // decoupled lookback -> incoming state r_in for this block
            float rin;
            if (blk == 0) {
                rin = r0v;
            } else {
                if (lane == 0) {
                    g_aggM[j][blk] = Mblk; g_aggB[j][blk] = Bblk;
                    __threadfence();
                    g_flag[j][blk] = 1;
                }
                float Mc = 1.0f, Bc = 0.0f;   // maps r_in(idx+1) -> r_in(blk)
                int idx = blk - 1;
                for (;;) {
                    int jj = idx - lane;
                    int fl = 1; float Mv = 1.0f, Bv = 0.0f;
                    if (jj >= 0) {
                        do { fl = g_flag[j][jj]; } while (fl == 0);
                        __threadfence();
                        if (fl == 2) { Mv = 0.0f; Bv = g_incR[j][jj]; }
                        else         { Mv = g_aggM[j][jj]; Bv = g_aggB[j][jj]; }
                    }
                    unsigned bal = __ballot_sync(0xFFFFFFFFu, (jj >= 0) && (fl == 2));
                    if (bal) {
                        int ls = __ffs(bal) - 1;     // nearest inclusive block
                        if (lane > ls) { Mv = 1.0f; Bv = 0.0f; }
                    }
                    // ordered reduction (lane0 outermost)
                    #pragma unroll
                    for (int off = 1; off < 32; off <<= 1) {
                        float Mo = __shfl_down_sync(0xFFFFFFFFu, Mv, off);
                        float Bo = __shfl_down_sync(0xFFFFFFFFu, Bv, off);
                        if (lane + off < 32) { Bv = fmaf(Mv, Bo, Bv); Mv *= Mo; }
                    }
                    if (lane == 0) { Bc = fmaf(Mc, Bv, Bc); Mc *= Mv; }
                    if (bal) break;
                    idx -= 32;
                }
                rin = __shfl_sync(0xFFFFFFFFu, Bc, 0);
            }
            if (lane == 0) {
                g_incR[j][blk] = fmaf(Mblk, rin, Bblk);
                __threadfence();
                g_flag[j][blk] = 2;
                *s_rin = rin;
            }
        }
        __syncthreads();

        // seed this thread's state and replay its steps
        const float rin = *s_rin;
        const float wm = s_wM[warp], wb = s_wB[warp];
        float r = fmaf(eM * wm, rin, fmaf(eM, wb, eB));

        if (last) {
            float ro[PER_TH];
            #pragma unroll
            for (int u = 0; u < PER_TH; u++) {
                float m = fmaf(-kk, ldt[u], 1.0f);
                r = fmaf(m, r, lb[u]);
                ro[u] = r;                         // r_predicts[i] = r_{i+1}
            }
            const int gi = blk * CHUNK + eb;
            if (gi + PER_TH <= N) {
                float4* o4 = reinterpret_cast<float4*>(out + gi);
                __stcs(&o4[0], make_float4(ro[0], ro[1], ro[2], ro[3]));
                __stcs(&o4[1], make_float4(ro[4], ro[5], ro[6], ro[7]));
            } else {
                for (int u = 0; u < PER_TH; u++)
                    if (gi + u < N) out[gi + u] = ro[u];
            }
        } else {
            #pragma unroll
            for (int u = 0; u < PER_TH; u++) {
                float m  = fmaf(-kk, ldt[u], 1.0f);
                float bc = lb[u];
                // next sweep's b uses r^{(j)}_i = current r (state entering step i)
                lb[u] = fmaf(lp[u], sqrtf(fabsf(r * ldt[u])), kth * ldt[u]);
                r = fmaf(m, r, bc);
            }
        }
        __syncthreads();   // protect s_wM/s_rin reuse by the next sweep
    }
}

// ---------------------------------------------------------------------------
extern "C" void kernel_launch(void* const* d_in, const int* in_sizes, int n_in,
                              void* d_out, int out_size)
{
    const float* trace = (const float*)d_in[0];
    const float* sW    = (const float*)d_in[1];
    const float* sb    = (const float*)d_in[2];
    const float* eW    = (const float*)d_in[3];
    const float* kp    = (const float*)d_in[4];
    const float* thp   = (const float*)d_in[5];
    float* out = (float*)d_out;

    int N    = out_size / 3;                       // 1048575
    int nblk = (N + CHUNK - 1) / CHUNK;            // 147 (one wave, 1 CTA/SM)

    size_t shbytes = (size_t)(4 + 2 * CHUNK + 2 * TILE_ROWS * FEAT + 72) * sizeof(float);
    cudaFuncSetAttribute(cir_main, cudaFuncAttributeMaxDynamicSharedMemorySize,
                         (int)shbytes);

    cir_main<<<nblk, THREADS, shbytes>>>(trace, sW, sb, eW, kp, thp, out, N);
}